// round 11
// baseline (speedup 1.0000x reference)
#include <cuda_runtime.h>
#include <cuda_bf16.h>
#include <math_constants.h>
#include <cstdint>

#define S_ 16384
#define K_ 4096
#define D_ 64
#define TEMP_ 50.0f
#define MAXEFF_ 5000.0f

// ---------------- scratch ----------------
__device__ float        g_e[(size_t)S_ * K_];     // exp'd (unnormalized) weights
__device__ unsigned int g_pmax[S_];
__device__ unsigned int g_nmax[S_];
__device__ float        g_zp[32 * S_];            // per-colblock z partials
__device__ float        g_vp[32 * S_];            // per-colblock v partials
// Fragment-packed tf32 splits {hi(t), hi(t+4), lo(t), lo(t+4)}:
__device__ float4 g_Xp[(size_t)S_ * 32];          // [row][d-slab][t]
__device__ float4 g_Yp1[K_ * 32];                 // [row][d-slab][t]
__device__ float4 g_Yt2[D_ * (K_ / 8) * 4];       // [d][k-slab][t]
// hi-only tables for pass1:
__device__ float2 g_Xh[(size_t)S_ * 32];
__device__ float2 g_Yh[K_ * 32];

#define NX  (S_ * 32)
#define NYA (K_ * 32)
#define NYT (D_ * (K_ / 8) * 4)

__device__ __forceinline__ unsigned int encf(float f) {
    unsigned int u = __float_as_uint(f);
    return (u & 0x80000000u) ? ~u : (u | 0x80000000u);
}
__device__ __forceinline__ float decf(unsigned int u) {
    return (u & 0x80000000u) ? __uint_as_float(u ^ 0x80000000u)
                             : __uint_as_float(~u);
}
__device__ __forceinline__ float tf32r(float x) {
    uint32_t u;
    asm("cvt.rna.tf32.f32 %0, %1;" : "=r"(u) : "f"(x));
    return __uint_as_float(u);
}
__device__ __forceinline__ void split1(float x, float& h, float& l) {
    h = tf32r(x);
    l = tf32r(x - h);
}
__device__ __forceinline__ float ex2(float x) {
    float r; asm("ex2.approx.ftz.f32 %0, %1;" : "=f"(r) : "f"(x)); return r;
}
__device__ __forceinline__ void mma8(float* c, const uint32_t* a,
                                     uint32_t b0, uint32_t b1) {
    asm volatile(
        "mma.sync.aligned.m16n8k8.row.col.f32.tf32.tf32.f32 "
        "{%0,%1,%2,%3}, {%4,%5,%6,%7}, {%8,%9}, {%0,%1,%2,%3};"
        : "+f"(c[0]), "+f"(c[1]), "+f"(c[2]), "+f"(c[3])
        : "r"(a[0]), "r"(a[1]), "r"(a[2]), "r"(a[3]), "r"(b0), "r"(b1));
}

// ---------------------------------------------------------------------------
// k_prepX: X tables.  k_prepY: Y tables (split so ncu idx3 = gemm kernel).
// ---------------------------------------------------------------------------
__global__ __launch_bounds__(256) void k_prepX(const float* __restrict__ X) {
    const int i = blockIdx.x * 256 + threadIdx.x;    // < NX
    int r = i >> 5, s = (i >> 2) & 7, t = i & 3;
    float h0, l0, h1, l1;
    split1(X[r * D_ + 8 * s + t],     h0, l0);
    split1(X[r * D_ + 8 * s + t + 4], h1, l1);
    g_Xp[i] = make_float4(h0, h1, l0, l1);
    g_Xh[i] = make_float2(h0, h1);
}
__global__ __launch_bounds__(256) void k_prepY(const float* __restrict__ Yw) {
    const int i = blockIdx.x * 256 + threadIdx.x;    // < NYA + NYT
    if (i < NYA) {
        int r = i >> 5, s = (i >> 2) & 7, t = i & 3;
        float h0, l0, h1, l1;
        split1(Yw[r * D_ + 8 * s + t],     h0, l0);
        split1(Yw[r * D_ + 8 * s + t + 4], h1, l1);
        g_Yp1[i] = make_float4(h0, h1, l0, l1);
        g_Yh[i]  = make_float2(h0, h1);
    } else {
        int j = i - NYA;
        int d = j >> 11, s = (j >> 2) & 511, t = j & 3;
        float h0, l0, h1, l1;
        split1(Yw[(8 * s + t) * D_ + d],     h0, l0);
        split1(Yw[(8 * s + t + 4) * D_ + d], h1, l1);
        g_Yt2[j] = make_float4(h0, h1, l0, l1);
    }
}

// ---------------------------------------------------------------------------
// k_pass1: row max/min of aff via 1x tf32 (R9-proven).
// ---------------------------------------------------------------------------
__global__ __launch_bounds__(256, 2) void k_pass1(const float* __restrict__ icpt)
{
    extern __shared__ float2 sp2[];
    float2* Ah = sp2;               // [128][36]
    float2* Bh = sp2 + 128 * 36;    // [128][36]

    const int tid = threadIdx.x;
    const int lane = tid & 31, wid = tid >> 5;
    const int wrow = (wid & 3) * 32;
    const int wn = (wid >> 2) * 64;
    const int g = lane >> 2, t = lane & 3;
    const int r0 = blockIdx.y * 128, c0 = blockIdx.x * 128;

    #pragma unroll
    for (int j = 0; j < 16; j++) {
        int f = tid + j * 256;
        int row = f >> 5, w = f & 31;
        Ah[row * 36 + w] = g_Xh[(size_t)(r0 + row) * 32 + w];
        Bh[row * 36 + w] = g_Yh[(c0 + row) * 32 + w];
    }
    __syncthreads();

    float acc[2][8][4];
    #pragma unroll
    for (int mt = 0; mt < 2; mt++)
        #pragma unroll
        for (int nt = 0; nt < 8; nt++)
            #pragma unroll
            for (int q = 0; q < 4; q++) acc[mt][nt][q] = 0.0f;

    #pragma unroll
    for (int s = 0; s < 8; s++) {
        uint32_t a_[2][4];
        #pragma unroll
        for (int mt = 0; mt < 2; mt++) {
            const int rb = wrow + mt * 16;
            float2 p0 = Ah[(rb + g) * 36 + s * 4 + t];
            float2 p1 = Ah[(rb + 8 + g) * 36 + s * 4 + t];
            a_[mt][0] = __float_as_uint(p0.x);
            a_[mt][1] = __float_as_uint(p1.x);
            a_[mt][2] = __float_as_uint(p0.y);
            a_[mt][3] = __float_as_uint(p1.y);
        }
        #pragma unroll
        for (int nt = 0; nt < 8; nt++) {
            float2 b = Bh[(wn + nt * 8 + g) * 36 + s * 4 + t];
            #pragma unroll
            for (int mt = 0; mt < 2; mt++)
                mma8(acc[mt][nt], a_[mt],
                     __float_as_uint(b.x), __float_as_uint(b.y));
        }
    }

    float mx[4] = {-CUDART_INF_F, -CUDART_INF_F, -CUDART_INF_F, -CUDART_INF_F};
    float mn[4] = { CUDART_INF_F,  CUDART_INF_F,  CUDART_INF_F,  CUDART_INF_F};

    #pragma unroll
    for (int mt = 0; mt < 2; mt++) {
        #pragma unroll
        for (int nt = 0; nt < 8; nt++) {
            const int c = c0 + wn + nt * 8 + 2 * t;
            float2 ic = __ldg((const float2*)(icpt + c));
            float o0 = acc[mt][nt][0] - ic.x;
            float o1 = acc[mt][nt][1] - ic.y;
            float o2 = acc[mt][nt][2] - ic.x;
            float o3 = acc[mt][nt][3] - ic.y;
            mx[mt*2]   = fmaxf(mx[mt*2],   fmaxf(o0, o1));
            mn[mt*2]   = fminf(mn[mt*2],   fminf(o0, o1));
            mx[mt*2+1] = fmaxf(mx[mt*2+1], fmaxf(o2, o3));
            mn[mt*2+1] = fminf(mn[mt*2+1], fminf(o2, o3));
        }
    }
    #pragma unroll
    for (int m = 1; m < 4; m <<= 1) {
        #pragma unroll
        for (int i = 0; i < 4; i++) {
            mx[i] = fmaxf(mx[i], __shfl_xor_sync(0xffffffffu, mx[i], m));
            mn[i] = fminf(mn[i], __shfl_xor_sync(0xffffffffu, mn[i], m));
        }
    }
    if (t == 0) {
        #pragma unroll
        for (int mt = 0; mt < 2; mt++) {
            const int row = r0 + wrow + mt * 16 + g;
            atomicMax(&g_pmax[row],     encf(mx[mt*2]));
            atomicMax(&g_nmax[row],     encf(-mn[mt*2]));
            atomicMax(&g_pmax[row + 8], encf(mx[mt*2+1]));
            atomicMax(&g_nmax[row + 8], encf(-mn[mt*2+1]));
        }
    }
}

// ---------------------------------------------------------------------------
// k_gemm_e: aff = X@Y^T - icpt (3x tf32); epilogue: e = exp(t*(aff-m)),
// store e, accumulate per-CTA z/v partials. 128x128 tile, 256 thr.
// ---------------------------------------------------------------------------
__global__ __launch_bounds__(256, 1) void k_gemm_e(const float* __restrict__ icpt)
{
    extern __shared__ float4 sm4[];
    float4* As = sm4;                 // [128][36]
    float4* Bs = sm4 + 128 * 36;      // [128][36]

    const int tid = threadIdx.x;
    const int lane = tid & 31, wid = tid >> 5;
    const int wrow = (wid & 3) * 32;
    const int wn = (wid >> 2) * 64;
    const int g = lane >> 2, t = lane & 3;
    const int r0 = blockIdx.y * 128, c0 = blockIdx.x * 128;

    #pragma unroll
    for (int j = 0; j < 16; j++) {
        int f = tid + j * 256;
        int row = f >> 5, w = f & 31;
        As[row * 36 + w] = g_Xp[(size_t)(r0 + row) * 32 + w];
        Bs[row * 36 + w] = g_Yp1[(c0 + row) * 32 + w];
    }
    __syncthreads();

    float acc[2][8][4];
    #pragma unroll
    for (int mt = 0; mt < 2; mt++)
        #pragma unroll
        for (int nt = 0; nt < 8; nt++)
            #pragma unroll
            for (int q = 0; q < 4; q++) acc[mt][nt][q] = 0.0f;

    #pragma unroll
    for (int s = 0; s < 8; s++) {
        uint32_t ah[2][4], al[2][4];
        #pragma unroll
        for (int mt = 0; mt < 2; mt++) {
            const int rb = wrow + mt * 16;
            uint4 q0 = *(const uint4*)&As[(rb + g) * 36 + s * 4 + t];
            uint4 q1 = *(const uint4*)&As[(rb + 8 + g) * 36 + s * 4 + t];
            ah[mt][0] = q0.x; ah[mt][1] = q1.x; ah[mt][2] = q0.y; ah[mt][3] = q1.y;
            al[mt][0] = q0.z; al[mt][1] = q1.z; al[mt][2] = q0.w; al[mt][3] = q1.w;
        }
        #pragma unroll
        for (int nt = 0; nt < 8; nt++) {
            uint4 bq = *(const uint4*)&Bs[(wn + nt * 8 + g) * 36 + s * 4 + t];
            #pragma unroll
            for (int mt = 0; mt < 2; mt++) {
                mma8(acc[mt][nt], ah[mt], bq.x, bq.y);
                mma8(acc[mt][nt], ah[mt], bq.z, bq.w);
                mma8(acc[mt][nt], al[mt], bq.x, bq.y);
            }
        }
    }
    __syncthreads();   // smem buffers dead; reused for z/v reduction below

    // per-thread row params (4 row-slots: mt*2 + j, j in {0 (+0), 1 (+8)})
    float mS[4], c1S[4];
    #pragma unroll
    for (int mt = 0; mt < 2; mt++)
        #pragma unroll
        for (int j = 0; j < 2; j++) {
            const int row = r0 + wrow + mt * 16 + g + 8 * j;
            float mxv = decf(g_pmax[row]);
            float mnv = -decf(g_nmax[row]);
            float span = fmaxf(mxv - mnv, 1e-3f);
            float tr = fminf(fmaxf(TEMP_ / span, TEMP_), MAXEFF_);
            c1S[mt*2+j] = tr * 1.4426950408889634f;
            mS[mt*2+j] = mxv;
        }

    float zv[4] = {0, 0, 0, 0}, vv[4] = {0, 0, 0, 0};

    #pragma unroll
    for (int mt = 0; mt < 2; mt++) {
        #pragma unroll
        for (int nt = 0; nt < 8; nt++) {
            const int c = c0 + wn + nt * 8 + 2 * t;
            float2 ic = __ldg((const float2*)(icpt + c));
            const int re = r0 + wrow + mt * 16 + g;
            float o0 = acc[mt][nt][0] - ic.x;
            float o1 = acc[mt][nt][1] - ic.y;
            float o2 = acc[mt][nt][2] - ic.x;
            float o3 = acc[mt][nt][3] - ic.y;
            float e0 = ex2(fminf((o0 - mS[mt*2])   * c1S[mt*2],   8.0f));
            float e1 = ex2(fminf((o1 - mS[mt*2])   * c1S[mt*2],   8.0f));
            float e2 = ex2(fminf((o2 - mS[mt*2+1]) * c1S[mt*2+1], 8.0f));
            float e3 = ex2(fminf((o3 - mS[mt*2+1]) * c1S[mt*2+1], 8.0f));
            zv[mt*2]   += e0 + e1;
            zv[mt*2+1] += e2 + e3;
            vv[mt*2]   = fmaf(e0, o0, fmaf(e1, o1, vv[mt*2]));
            vv[mt*2+1] = fmaf(e2, o2, fmaf(e3, o3, vv[mt*2+1]));
            *(float2*)(g_e + (size_t)re * K_ + c)       = make_float2(e0, e1);
            *(float2*)(g_e + (size_t)(re + 8) * K_ + c) = make_float2(e2, e3);
        }
    }
    // reduce over the 4 t-lanes
    #pragma unroll
    for (int m = 1; m < 4; m <<= 1) {
        #pragma unroll
        for (int i = 0; i < 4; i++) {
            zv[i] += __shfl_xor_sync(0xffffffffu, zv[i], m);
            vv[i] += __shfl_xor_sync(0xffffffffu, vv[i], m);
        }
    }
    float* Zp = (float*)sm4;          // [128][2]
    float* Vp = Zp + 256;             // [128][2]
    if (t == 0) {
        const int grp = wid >> 2;
        #pragma unroll
        for (int mt = 0; mt < 2; mt++)
            #pragma unroll
            for (int j = 0; j < 2; j++) {
                const int row = wrow + mt * 16 + g + 8 * j;
                Zp[row * 2 + grp] = zv[mt*2+j];
                Vp[row * 2 + grp] = vv[mt*2+j];
            }
    }
    __syncthreads();
    if (tid < 128) {
        g_zp[blockIdx.x * S_ + r0 + tid] = Zp[tid * 2] + Zp[tid * 2 + 1];
        g_vp[blockIdx.x * S_ + r0 + tid] = Vp[tid * 2] + Vp[tid * 2 + 1];
    }
}

// ---------------------------------------------------------------------------
// k_soft: pure GEMM choice = (e @ Y) / Z.  64-row CTAs (grid 256, 2/SM),
// 256 thr = 4 row-warps x 2 k-groups; 32-k chunks double-buffered for both
// operands; register-side tf32 split between LDS and MMA.
// ---------------------------------------------------------------------------
__global__ __launch_bounds__(256, 2) void k_soft(
    float* __restrict__ out_choice, float* __restrict__ out_v)
{
    extern __shared__ float sbf[];
    float*  E  = sbf;                        // 2 x [64][36]
    float4* Yb = (float4*)(sbf + 2 * 64 * 36);   // 2 x [64][20] f4
    float*  Zi = sbf + 2 * 64 * 36 + 2 * 1280 * 4;  // [64]

    const int tid = threadIdx.x;
    const int lane = tid & 31, wid = tid >> 5;
    const int kg = wid >> 2;                 // 0/1
    const int rb = (wid & 3) * 16;           // 16 rows per warp
    const int g = lane >> 2, t = lane & 3;
    const int r0 = blockIdx.x * 64;

    // Z/v reduction over 32 colblock partials (deterministic order)
    if (tid < 64) {
        float z = 0.0f, v = 0.0f;
        #pragma unroll 8
        for (int cb = 0; cb < 32; cb++) {
            z += g_zp[cb * S_ + r0 + tid];
            v += g_vp[cb * S_ + r0 + tid];
        }
        Zi[tid] = 1.0f / z;
        out_v[r0 + tid] = v / z;
    }

    auto stageE = [&](int ck, int buf) {
        float* dst = E + buf * (64 * 36);
        const float4* src = (const float4*)g_e;
        #pragma unroll
        for (int j = 0; j < 2; j++) {
            int f = tid + j * 256;           // 512 f4
            int row = f >> 3, c4 = f & 7;
            float4 v4 = __ldg(src + (size_t)(r0 + row) * 1024 + ck * 8 + c4);
            *(float4*)&dst[row * 36 + 4 * c4] = v4;
        }
    };
    auto stageY = [&](int ck, int buf) {
        float4* dst = Yb + buf * 1280;
        #pragma unroll
        for (int j = 0; j < 4; j++) {
            int f = tid + j * 256;           // 1024 f4
            int d = f >> 4, w = f & 15;
            dst[d * 20 + w] = __ldg(&g_Yt2[d * 2048 + ck * 16 + w]);
        }
    };

    float acc[8][4];
    #pragma unroll
    for (int nt = 0; nt < 8; nt++)
        #pragma unroll
        for (int q = 0; q < 4; q++) acc[nt][q] = 0.0f;

    stageE(0, 0);
    stageY(0, 0);
    __syncthreads();

    for (int ck = 0; ck < 128; ck++) {
        const int cur = ck & 1;
        if (ck + 1 < 128) {
            stageE(ck + 1, cur ^ 1);
            stageY(ck + 1, cur ^ 1);
        }
        const float*  Ec = E + cur * (64 * 36);
        const float4* Yc = Yb + cur * 1280;

        #pragma unroll
        for (int s = 0; s < 2; s++) {
            const int kcol = kg * 16 + s * 8;
            float e0 = Ec[(rb + g) * 36 + kcol + t];
            float e1 = Ec[(rb + 8 + g) * 36 + kcol + t];
            float e2 = Ec[(rb + g) * 36 + kcol + t + 4];
            float e3 = Ec[(rb + 8 + g) * 36 + kcol + t + 4];
            uint32_t ah[4], al[4];
            float h, l;
            split1(e0, h, l); ah[0] = __float_as_uint(h); al[0] = __float_as_uint(l);
            split1(e1, h, l); ah[1] = __float_as_uint(h); al[1] = __float_as_uint(l);
            split1(e2, h, l); ah[2] = __float_as_uint(h); al[2] = __float_as_uint(l);
            split1(e3, h, l); ah[3] = __float_as_uint(h); al[3] = __float_as_uint(l);
            #pragma unroll
            for (int nt = 0; nt < 8; nt++) {
                uint4 bq = *(const uint4*)&Yc[(nt * 8 + g) * 20 + kg * 8 + s * 4 + t];
                mma8(acc[nt], ah, bq.x, bq.y);
                mma8(acc[nt], ah, bq.z, bq.w);
                mma8(acc[nt], al, bq.x, bq.y);
            }
        }
        __syncthreads();
    }

    // cross-kg reduction through (dead) E-buffer smem
    float* Rch = sbf;                 // [64][66] aliases E region (4224 < 4608)
    if (kg == 1) {
        #pragma unroll
        for (int nt = 0; nt < 8; nt++) {
            const int col = nt * 8 + 2 * t;
            *(float2*)&Rch[(rb + g) * 66 + col]     = make_float2(acc[nt][0], acc[nt][1]);
            *(float2*)&Rch[(rb + 8 + g) * 66 + col] = make_float2(acc[nt][2], acc[nt][3]);
        }
    }
    __syncthreads();
    if (kg == 0) {
        const float inv0 = Zi[rb + g];
        const float inv1 = Zi[rb + 8 + g];
        #pragma unroll
        for (int nt = 0; nt < 8; nt++) {
            const int col = nt * 8 + 2 * t;
            float2 p0 = *(const float2*)&Rch[(rb + g) * 66 + col];
            float2 p1 = *(const float2*)&Rch[(rb + 8 + g) * 66 + col];
            *(float2*)(out_choice + (size_t)(r0 + rb + g) * D_ + col) =
                make_float2((acc[nt][0] + p0.x) * inv0, (acc[nt][1] + p0.y) * inv0);
            *(float2*)(out_choice + (size_t)(r0 + rb + 8 + g) * D_ + col) =
                make_float2((acc[nt][2] + p1.x) * inv1, (acc[nt][3] + p1.y) * inv1);
        }
    }
}

// ---------------------------------------------------------------------------
extern "C" void kernel_launch(void* const* d_in, const int* in_sizes, int n_in,
                              void* d_out, int out_size) {
    const float* X    = (const float*)d_in[0];
    const float* Yw   = (const float*)d_in[1];
    const float* icpt = (const float*)d_in[2];
    float* out        = (float*)d_out;
    float* out_choice = out;
    float* out_v      = out + (size_t)S_ * D_;

    const int smem1 = 2 * 128 * 36 * 8;                    // 73,728
    const int smemG = 2 * 128 * 36 * 16;                   // 147,456
    const int smemS = (2 * 64 * 36 + 2 * 1280 * 4 + 64) * 4;  // 59,648
    cudaFuncSetAttribute(k_pass1, cudaFuncAttributeMaxDynamicSharedMemorySize, smem1);
    cudaFuncSetAttribute(k_gemm_e, cudaFuncAttributeMaxDynamicSharedMemorySize, smemG);
    cudaFuncSetAttribute(k_soft,  cudaFuncAttributeMaxDynamicSharedMemorySize, smemS);

    k_prepX<<<NX / 256, 256>>>(X);                          // launch 0
    k_prepY<<<(NYA + NYT) / 256, 256>>>(Yw);                // launch 1

    dim3 g1(K_ / 128, S_ / 128);
    k_pass1<<<g1, 256, smem1>>>(icpt);                      // launch 2
    k_gemm_e<<<g1, 256, smemG>>>(icpt);                     // launch 3  <- ncu
    k_soft<<<S_ / 64, 256, smemS>>>(out_choice, out_v);     // launch 4
}

// round 12
// speedup vs baseline: 1.0629x; 1.0629x over previous
#include <cuda_runtime.h>
#include <cuda_bf16.h>
#include <math_constants.h>
#include <cstdint>

#define S_ 16384
#define K_ 4096
#define D_ 64
#define TEMP_ 50.0f
#define MAXEFF_ 5000.0f

// ---------------- scratch ----------------
__device__ float        g_e[(size_t)S_ * K_];     // exp'd (unnormalized) weights
__device__ unsigned int g_pmax[S_];
__device__ unsigned int g_nmax[S_];
__device__ float        g_zp[64 * S_];            // per-colblock z partials
__device__ float        g_vp[64 * S_];            // per-colblock v partials
// Fragment-packed tf32 splits {hi(t), hi(t+4), lo(t), lo(t+4)}:
__device__ float4 g_Xp[(size_t)S_ * 32];          // [row][d-slab][t]
__device__ float4 g_Yp1[K_ * 32];                 // [row][d-slab][t]
__device__ float4 g_Yt2[D_ * (K_ / 8) * 4];       // [d][k-slab][t]
// hi-only tables for pass1:
__device__ float2 g_Xh[(size_t)S_ * 32];
__device__ float2 g_Yh[K_ * 32];

#define NX  (S_ * 32)
#define NYA (K_ * 32)
#define NYT (D_ * (K_ / 8) * 4)

__device__ __forceinline__ unsigned int encf(float f) {
    unsigned int u = __float_as_uint(f);
    return (u & 0x80000000u) ? ~u : (u | 0x80000000u);
}
__device__ __forceinline__ float decf(unsigned int u) {
    return (u & 0x80000000u) ? __uint_as_float(u ^ 0x80000000u)
                             : __uint_as_float(~u);
}
__device__ __forceinline__ float tf32r(float x) {
    uint32_t u;
    asm("cvt.rna.tf32.f32 %0, %1;" : "=r"(u) : "f"(x));
    return __uint_as_float(u);
}
__device__ __forceinline__ void split1(float x, float& h, float& l) {
    h = tf32r(x);
    l = tf32r(x - h);
}
__device__ __forceinline__ float ex2(float x) {
    float r; asm("ex2.approx.ftz.f32 %0, %1;" : "=f"(r) : "f"(x)); return r;
}
__device__ __forceinline__ void mma8(float* c, const uint32_t* a,
                                     uint32_t b0, uint32_t b1) {
    asm volatile(
        "mma.sync.aligned.m16n8k8.row.col.f32.tf32.tf32.f32 "
        "{%0,%1,%2,%3}, {%4,%5,%6,%7}, {%8,%9}, {%0,%1,%2,%3};"
        : "+f"(c[0]), "+f"(c[1]), "+f"(c[2]), "+f"(c[3])
        : "r"(a[0]), "r"(a[1]), "r"(a[2]), "r"(a[3]), "r"(b0), "r"(b1));
}

// ---------------------------------------------------------------------------
// k_prepX / k_prepY: packed split tables.
// ---------------------------------------------------------------------------
__global__ __launch_bounds__(256) void k_prepX(const float* __restrict__ X) {
    const int i = blockIdx.x * 256 + threadIdx.x;    // < NX
    int r = i >> 5, s = (i >> 2) & 7, t = i & 3;
    float h0, l0, h1, l1;
    split1(X[r * D_ + 8 * s + t],     h0, l0);
    split1(X[r * D_ + 8 * s + t + 4], h1, l1);
    g_Xp[i] = make_float4(h0, h1, l0, l1);
    g_Xh[i] = make_float2(h0, h1);
}
__global__ __launch_bounds__(256) void k_prepY(const float* __restrict__ Yw) {
    const int i = blockIdx.x * 256 + threadIdx.x;    // < NYA + NYT
    if (i < NYA) {
        int r = i >> 5, s = (i >> 2) & 7, t = i & 3;
        float h0, l0, h1, l1;
        split1(Yw[r * D_ + 8 * s + t],     h0, l0);
        split1(Yw[r * D_ + 8 * s + t + 4], h1, l1);
        g_Yp1[i] = make_float4(h0, h1, l0, l1);
        g_Yh[i]  = make_float2(h0, h1);
    } else {
        int j = i - NYA;
        int d = j >> 11, s = (j >> 2) & 511, t = j & 3;
        float h0, l0, h1, l1;
        split1(Yw[(8 * s + t) * D_ + d],     h0, l0);
        split1(Yw[(8 * s + t + 4) * D_ + d], h1, l1);
        g_Yt2[j] = make_float4(h0, h1, l0, l1);
    }
}

// ---------------------------------------------------------------------------
// k_pass1: row max/min of aff via 1x tf32 (precision-sufficient, R9-proven).
// ---------------------------------------------------------------------------
__global__ __launch_bounds__(256, 2) void k_pass1(const float* __restrict__ icpt)
{
    extern __shared__ float2 sp2[];
    float2* Ah = sp2;               // [128][36]
    float2* Bh = sp2 + 128 * 36;    // [128][36]

    const int tid = threadIdx.x;
    const int lane = tid & 31, wid = tid >> 5;
    const int wrow = (wid & 3) * 32;
    const int wn = (wid >> 2) * 64;
    const int g = lane >> 2, t = lane & 3;
    const int r0 = blockIdx.y * 128, c0 = blockIdx.x * 128;

    #pragma unroll
    for (int j = 0; j < 16; j++) {
        int f = tid + j * 256;
        int row = f >> 5, w = f & 31;
        Ah[row * 36 + w] = g_Xh[(size_t)(r0 + row) * 32 + w];
        Bh[row * 36 + w] = g_Yh[(c0 + row) * 32 + w];
    }
    __syncthreads();

    float acc[2][8][4];
    #pragma unroll
    for (int mt = 0; mt < 2; mt++)
        #pragma unroll
        for (int nt = 0; nt < 8; nt++)
            #pragma unroll
            for (int q = 0; q < 4; q++) acc[mt][nt][q] = 0.0f;

    #pragma unroll
    for (int s = 0; s < 8; s++) {
        uint32_t a_[2][4];
        #pragma unroll
        for (int mt = 0; mt < 2; mt++) {
            const int rb = wrow + mt * 16;
            float2 p0 = Ah[(rb + g) * 36 + s * 4 + t];
            float2 p1 = Ah[(rb + 8 + g) * 36 + s * 4 + t];
            a_[mt][0] = __float_as_uint(p0.x);
            a_[mt][1] = __float_as_uint(p1.x);
            a_[mt][2] = __float_as_uint(p0.y);
            a_[mt][3] = __float_as_uint(p1.y);
        }
        #pragma unroll
        for (int nt = 0; nt < 8; nt++) {
            float2 b = Bh[(wn + nt * 8 + g) * 36 + s * 4 + t];
            #pragma unroll
            for (int mt = 0; mt < 2; mt++)
                mma8(acc[mt][nt], a_[mt],
                     __float_as_uint(b.x), __float_as_uint(b.y));
        }
    }

    float mx[4] = {-CUDART_INF_F, -CUDART_INF_F, -CUDART_INF_F, -CUDART_INF_F};
    float mn[4] = { CUDART_INF_F,  CUDART_INF_F,  CUDART_INF_F,  CUDART_INF_F};

    #pragma unroll
    for (int mt = 0; mt < 2; mt++) {
        #pragma unroll
        for (int nt = 0; nt < 8; nt++) {
            const int c = c0 + wn + nt * 8 + 2 * t;
            float2 ic = __ldg((const float2*)(icpt + c));
            float o0 = acc[mt][nt][0] - ic.x;
            float o1 = acc[mt][nt][1] - ic.y;
            float o2 = acc[mt][nt][2] - ic.x;
            float o3 = acc[mt][nt][3] - ic.y;
            mx[mt*2]   = fmaxf(mx[mt*2],   fmaxf(o0, o1));
            mn[mt*2]   = fminf(mn[mt*2],   fminf(o0, o1));
            mx[mt*2+1] = fmaxf(mx[mt*2+1], fmaxf(o2, o3));
            mn[mt*2+1] = fminf(mn[mt*2+1], fminf(o2, o3));
        }
    }
    #pragma unroll
    for (int m = 1; m < 4; m <<= 1) {
        #pragma unroll
        for (int i = 0; i < 4; i++) {
            mx[i] = fmaxf(mx[i], __shfl_xor_sync(0xffffffffu, mx[i], m));
            mn[i] = fminf(mn[i], __shfl_xor_sync(0xffffffffu, mn[i], m));
        }
    }
    if (t == 0) {
        #pragma unroll
        for (int mt = 0; mt < 2; mt++) {
            const int row = r0 + wrow + mt * 16 + g;
            atomicMax(&g_pmax[row],     encf(mx[mt*2]));
            atomicMax(&g_nmax[row],     encf(-mn[mt*2]));
            atomicMax(&g_pmax[row + 8], encf(mx[mt*2+1]));
            atomicMax(&g_nmax[row + 8], encf(-mn[mt*2+1]));
        }
    }
}

// ---------------------------------------------------------------------------
// k_gemm_e: aff = X@Y^T - icpt (3x tf32); epilogue exp + z/v partials.
// Tile 128M x 64N, 256 thr, smem 110.6KB -> 2 CTA/SM (phase overlap).
// ---------------------------------------------------------------------------
__global__ __launch_bounds__(256, 2) void k_gemm_e(const float* __restrict__ icpt)
{
    extern __shared__ float4 sm4[];
    float4* As = sm4;                 // [128][36]
    float4* Bs = sm4 + 128 * 36;      // [64][36]

    const int tid = threadIdx.x;
    const int lane = tid & 31, wid = tid >> 5;
    const int wrow = (wid & 3) * 32;
    const int wn = (wid >> 2) * 32;   // 2 col-groups of 32
    const int g = lane >> 2, t = lane & 3;
    const int r0 = blockIdx.y * 128, c0 = blockIdx.x * 64;

    #pragma unroll
    for (int j = 0; j < 16; j++) {
        int f = tid + j * 256;
        int row = f >> 5, w = f & 31;
        As[row * 36 + w] = g_Xp[(size_t)(r0 + row) * 32 + w];
    }
    #pragma unroll
    for (int j = 0; j < 8; j++) {
        int f = tid + j * 256;
        int row = f >> 5, w = f & 31;
        Bs[row * 36 + w] = g_Yp1[(c0 + row) * 32 + w];
    }
    __syncthreads();

    float acc[2][4][4];
    #pragma unroll
    for (int mt = 0; mt < 2; mt++)
        #pragma unroll
        for (int nt = 0; nt < 4; nt++)
            #pragma unroll
            for (int q = 0; q < 4; q++) acc[mt][nt][q] = 0.0f;

    #pragma unroll
    for (int s = 0; s < 8; s++) {
        uint32_t ah[2][4], al[2][4];
        #pragma unroll
        for (int mt = 0; mt < 2; mt++) {
            const int rb = wrow + mt * 16;
            uint4 q0 = *(const uint4*)&As[(rb + g) * 36 + s * 4 + t];
            uint4 q1 = *(const uint4*)&As[(rb + 8 + g) * 36 + s * 4 + t];
            ah[mt][0] = q0.x; ah[mt][1] = q1.x; ah[mt][2] = q0.y; ah[mt][3] = q1.y;
            al[mt][0] = q0.z; al[mt][1] = q1.z; al[mt][2] = q0.w; al[mt][3] = q1.w;
        }
        #pragma unroll
        for (int nt = 0; nt < 4; nt++) {
            uint4 bq = *(const uint4*)&Bs[(wn + nt * 8 + g) * 36 + s * 4 + t];
            #pragma unroll
            for (int mt = 0; mt < 2; mt++) {
                mma8(acc[mt][nt], ah[mt], bq.x, bq.y);
                mma8(acc[mt][nt], ah[mt], bq.z, bq.w);
                mma8(acc[mt][nt], al[mt], bq.x, bq.y);
            }
        }
    }
    __syncthreads();   // smem buffers dead; reused for z/v reduction below

    // per-thread row params
    float mS[4], c1S[4];
    #pragma unroll
    for (int mt = 0; mt < 2; mt++)
        #pragma unroll
        for (int j = 0; j < 2; j++) {
            const int row = r0 + wrow + mt * 16 + g + 8 * j;
            float mxv = decf(g_pmax[row]);
            float mnv = -decf(g_nmax[row]);
            float span = fmaxf(mxv - mnv, 1e-3f);
            float tr = fminf(fmaxf(TEMP_ / span, TEMP_), MAXEFF_);
            c1S[mt*2+j] = tr * 1.4426950408889634f;
            mS[mt*2+j] = mxv;
        }

    float zv[4] = {0, 0, 0, 0}, vv[4] = {0, 0, 0, 0};

    #pragma unroll
    for (int mt = 0; mt < 2; mt++) {
        #pragma unroll
        for (int nt = 0; nt < 4; nt++) {
            const int c = c0 + wn + nt * 8 + 2 * t;
            float2 ic = __ldg((const float2*)(icpt + c));
            const int re = r0 + wrow + mt * 16 + g;
            float o0 = acc[mt][nt][0] - ic.x;
            float o1 = acc[mt][nt][1] - ic.y;
            float o2 = acc[mt][nt][2] - ic.x;
            float o3 = acc[mt][nt][3] - ic.y;
            float e0 = ex2(fminf((o0 - mS[mt*2])   * c1S[mt*2],   8.0f));
            float e1 = ex2(fminf((o1 - mS[mt*2])   * c1S[mt*2],   8.0f));
            float e2 = ex2(fminf((o2 - mS[mt*2+1]) * c1S[mt*2+1], 8.0f));
            float e3 = ex2(fminf((o3 - mS[mt*2+1]) * c1S[mt*2+1], 8.0f));
            zv[mt*2]   += e0 + e1;
            zv[mt*2+1] += e2 + e3;
            vv[mt*2]   = fmaf(e0, o0, fmaf(e1, o1, vv[mt*2]));
            vv[mt*2+1] = fmaf(e2, o2, fmaf(e3, o3, vv[mt*2+1]));
            *(float2*)(g_e + (size_t)re * K_ + c)       = make_float2(e0, e1);
            *(float2*)(g_e + (size_t)(re + 8) * K_ + c) = make_float2(e2, e3);
        }
    }
    // reduce over the 4 t-lanes
    #pragma unroll
    for (int m = 1; m < 4; m <<= 1) {
        #pragma unroll
        for (int i = 0; i < 4; i++) {
            zv[i] += __shfl_xor_sync(0xffffffffu, zv[i], m);
            vv[i] += __shfl_xor_sync(0xffffffffu, vv[i], m);
        }
    }
    float* Zp = (float*)sm4;          // [128][2]
    float* Vp = Zp + 256;             // [128][2]
    if (t == 0) {
        const int grp = wid >> 2;
        #pragma unroll
        for (int mt = 0; mt < 2; mt++)
            #pragma unroll
            for (int j = 0; j < 2; j++) {
                const int row = wrow + mt * 16 + g + 8 * j;
                Zp[row * 2 + grp] = zv[mt*2+j];
                Vp[row * 2 + grp] = vv[mt*2+j];
            }
    }
    __syncthreads();
    if (tid < 128) {
        g_zp[blockIdx.x * S_ + r0 + tid] = Zp[tid * 2] + Zp[tid * 2 + 1];
        g_vp[blockIdx.x * S_ + r0 + tid] = Vp[tid * 2] + Vp[tid * 2 + 1];
    }
}

// ---------------------------------------------------------------------------
// k_soft: pure GEMM choice = (e @ Y) / Z.  64-row CTAs, 2 CTA/SM,
// 256 thr = 4 row-warps x 2 k-groups; double-buffered operand staging.
// ---------------------------------------------------------------------------
__global__ __launch_bounds__(256, 2) void k_soft(
    float* __restrict__ out_choice, float* __restrict__ out_v)
{
    extern __shared__ float sbf[];
    float*  E  = sbf;                        // 2 x [64][36]
    float4* Yb = (float4*)(sbf + 2 * 64 * 36);   // 2 x [64][20] f4
    float*  Zi = sbf + 2 * 64 * 36 + 2 * 1280 * 4;  // [64]

    const int tid = threadIdx.x;
    const int lane = tid & 31, wid = tid >> 5;
    const int kg = wid >> 2;                 // 0/1
    const int rb = (wid & 3) * 16;           // 16 rows per warp
    const int g = lane >> 2, t = lane & 3;
    const int r0 = blockIdx.x * 64;

    // Z/v reduction over 64 colblock partials (deterministic order)
    if (tid < 64) {
        float z = 0.0f, v = 0.0f;
        #pragma unroll 8
        for (int cb = 0; cb < 64; cb++) {
            z += g_zp[cb * S_ + r0 + tid];
            v += g_vp[cb * S_ + r0 + tid];
        }
        Zi[tid] = 1.0f / z;
        out_v[r0 + tid] = v / z;
    }

    auto stageE = [&](int ck, int buf) {
        float* dst = E + buf * (64 * 36);
        const float4* src = (const float4*)g_e;
        #pragma unroll
        for (int j = 0; j < 2; j++) {
            int f = tid + j * 256;           // 512 f4
            int row = f >> 3, c4 = f & 7;
            float4 v4 = __ldg(src + (size_t)(r0 + row) * 1024 + ck * 8 + c4);
            *(float4*)&dst[row * 36 + 4 * c4] = v4;
        }
    };
    auto stageY = [&](int ck, int buf) {
        float4* dst = Yb + buf * 1280;
        #pragma unroll
        for (int j = 0; j < 4; j++) {
            int f = tid + j * 256;           // 1024 f4
            int d = f >> 4, w = f & 15;
            dst[d * 20 + w] = __ldg(&g_Yt2[d * 2048 + ck * 16 + w]);
        }
    };

    float acc[8][4];
    #pragma unroll
    for (int nt = 0; nt < 8; nt++)
        #pragma unroll
        for (int q = 0; q < 4; q++) acc[nt][q] = 0.0f;

    stageE(0, 0);
    stageY(0, 0);
    __syncthreads();

    for (int ck = 0; ck < 128; ck++) {
        const int cur = ck & 1;
        if (ck + 1 < 128) {
            stageE(ck + 1, cur ^ 1);
            stageY(ck + 1, cur ^ 1);
        }
        const float*  Ec = E + cur * (64 * 36);
        const float4* Yc = Yb + cur * 1280;

        #pragma unroll
        for (int s = 0; s < 2; s++) {
            const int kcol = kg * 16 + s * 8;
            float e0 = Ec[(rb + g) * 36 + kcol + t];
            float e1 = Ec[(rb + 8 + g) * 36 + kcol + t];
            float e2 = Ec[(rb + g) * 36 + kcol + t + 4];
            float e3 = Ec[(rb + 8 + g) * 36 + kcol + t + 4];
            uint32_t ah[4], al[4];
            float h, l;
            split1(e0, h, l); ah[0] = __float_as_uint(h); al[0] = __float_as_uint(l);
            split1(e1, h, l); ah[1] = __float_as_uint(h); al[1] = __float_as_uint(l);
            split1(e2, h, l); ah[2] = __float_as_uint(h); al[2] = __float_as_uint(l);
            split1(e3, h, l); ah[3] = __float_as_uint(h); al[3] = __float_as_uint(l);
            #pragma unroll
            for (int nt = 0; nt < 8; nt++) {
                uint4 bq = *(const uint4*)&Yc[(nt * 8 + g) * 20 + kg * 8 + s * 4 + t];
                mma8(acc[nt], ah, bq.x, bq.y);
                mma8(acc[nt], ah, bq.z, bq.w);
                mma8(acc[nt], al, bq.x, bq.y);
            }
        }
        __syncthreads();
    }

    // cross-kg reduction through (dead) E-buffer smem
    float* Rch = sbf;                 // [64][66]
    if (kg == 1) {
        #pragma unroll
        for (int nt = 0; nt < 8; nt++) {
            const int col = nt * 8 + 2 * t;
            *(float2*)&Rch[(rb + g) * 66 + col]     = make_float2(acc[nt][0], acc[nt][1]);
            *(float2*)&Rch[(rb + 8 + g) * 66 + col] = make_float2(acc[nt][2], acc[nt][3]);
        }
    }
    __syncthreads();
    if (kg == 0) {
        const float inv0 = Zi[rb + g];
        const float inv1 = Zi[rb + 8 + g];
        #pragma unroll
        for (int nt = 0; nt < 8; nt++) {
            const int col = nt * 8 + 2 * t;
            float2 p0 = *(const float2*)&Rch[(rb + g) * 66 + col];
            float2 p1 = *(const float2*)&Rch[(rb + 8 + g) * 66 + col];
            *(float2*)(out_choice + (size_t)(r0 + rb + g) * D_ + col) =
                make_float2((acc[nt][0] + p0.x) * inv0, (acc[nt][1] + p0.y) * inv0);
            *(float2*)(out_choice + (size_t)(r0 + rb + 8 + g) * D_ + col) =
                make_float2((acc[nt][2] + p1.x) * inv1, (acc[nt][3] + p1.y) * inv1);
        }
    }
}

// ---------------------------------------------------------------------------
extern "C" void kernel_launch(void* const* d_in, const int* in_sizes, int n_in,
                              void* d_out, int out_size) {
    const float* X    = (const float*)d_in[0];
    const float* Yw   = (const float*)d_in[1];
    const float* icpt = (const float*)d_in[2];
    float* out        = (float*)d_out;
    float* out_choice = out;
    float* out_v      = out + (size_t)S_ * D_;

    const int smem1 = 2 * 128 * 36 * 8;                    // 73,728
    const int smemG = (128 * 36 + 64 * 36) * 16;           // 110,592
    const int smemS = (2 * 64 * 36 + 2 * 1280 * 4 + 64) * 4;  // 59,648
    cudaFuncSetAttribute(k_pass1, cudaFuncAttributeMaxDynamicSharedMemorySize, smem1);
    cudaFuncSetAttribute(k_gemm_e, cudaFuncAttributeMaxDynamicSharedMemorySize, smemG);
    cudaFuncSetAttribute(k_soft,  cudaFuncAttributeMaxDynamicSharedMemorySize, smemS);

    k_prepX<<<NX / 256, 256>>>(X);                          // launch 0
    k_prepY<<<(NYA + NYT) / 256, 256>>>(Yw);                // launch 1

    dim3 gp(K_ / 128, S_ / 128);
    k_pass1<<<gp, 256, smem1>>>(icpt);                      // launch 2

    dim3 ge(K_ / 64, S_ / 128);
    k_gemm_e<<<ge, 256, smemG>>>(icpt);                     // launch 3  <- ncu
    k_soft<<<S_ / 64, 256, smemS>>>(out_choice, out_v);     // launch 4
}